// round 14
// baseline (speedup 1.0000x reference)
#include <cuda_runtime.h>

#define NN 256
#define BB 64
#define FBIG 1e8f
#define K2   144.269504089f     // (1/gamma)*log2(e), gamma = 0.01
#define GLN2 0.006931471806f    // gamma*ln(2)
#define FULL 0xffffffffu

// Softmin-weight scratch: [batch][col-1][group] x {float4 lo, float4 hi}
//   lo=(wu0,wl0,wu1,wl1)  hi=(wu2,wl2,wu3,wl3)  for rows 4g+1..4g+4
// wd = 1-wu-wl. Backward reads col 255-2p / 254-2p, group 63-V, row r<->3-r.
// 64*256*64*2*16B = 33.5 MB -> L2-resident.
__device__ float4 g_W[(size_t)BB * 256 * 64 * 2];
__device__ float g_partV[BB];
__device__ float g_partE[BB];
__device__ unsigned g_ticket = 0;

__device__ __forceinline__ float ex2(float x){ float r; asm("ex2.approx.f32 %0,%1;":"=f"(r):"f"(x)); return r; }
__device__ __forceinline__ float lg2(float x){ float r; asm("lg2.approx.f32 %0,%1;":"=f"(r):"f"(x)); return r; }
__device__ __forceinline__ float rcpa(float x){ float r; asm("rcp.approx.f32 %0,%1;":"=f"(r):"f"(x)); return r; }

__global__ __launch_bounds__(64, 1) void dilate_fb_kernel(
    const float* __restrict__ y_pred,
    const float* __restrict__ y_true,
    float* __restrict__ out)
{
    __shared__ float s_o[NN], s_t[NN];
    __shared__ float s_f[2][4];       // fwd cross-warp handoff (mA,wA,mB,wB), parity
    __shared__ float s_b[2][4];       // bwd cross-warp handoff (puA,puB,pdA,pdB)
    __shared__ float s_red[2];
    __shared__ float s_vnn;
    __shared__ int   s_last;

    const int b   = blockIdx.x;
    const int tid = threadIdx.x;      // virtual lane V; owns rows 4V+1..4V+4
    const int w   = tid >> 5;
    const int l   = tid & 31;

    for (int x = tid; x < NN; x += 64) {
        s_o[x] = y_pred[b * NN + x];
        s_t[x] = y_true[b * NN + x];
    }
    __syncthreads();

    float ti[4];
    #pragma unroll
    for (int r = 0; r < 4; ++r) ti[r] = s_t[4 * tid + r];
    float4* __restrict__ Wb = g_W + (size_t)b * (256 * 64 * 2);

    // ===== FORWARD: (m,w) soft-min, 4 rows/lane, 2 cols/iteration ==============
    // lane V at iter n: pair p = n-V, cols 2p+1 and 2p+2 (1-indexed).
    {
        float mm[4], ww[4];
        #pragma unroll
        for (int r = 0; r < 4; ++r) { mm[r] = FBIG; ww[r] = 1.0f; }
        float rxmA = FBIG, rxwA = 1.0f, rxmB = FBIG, rxwB = 1.0f;
        float holdm = FBIG, holdw = 1.0f;
        float lzmA = FBIG, lzwA = 1.0f, lzmB = FBIG, lzwB = 1.0f;
        float lzhm = FBIG, lzhw = 1.0f;

        for (int cc = 0; cc < 48; ++cc) {
            #pragma unroll
            for (int k = 0; k < 4; ++k) {
                const int n = cc * 4 + k;
                const int p = n - tid;
                const bool act   = (unsigned)p < 128u;
                const bool first = (n == tid);
                if (first) {
                    #pragma unroll
                    for (int r = 0; r < 4; ++r) { mm[r] = FBIG; ww[r] = 1.0f; }
                }
                float umA, uwA, dmA, dwA, umB, uwB, dmB, dwB;
                if (tid == 0) {                 // up row = row0: all FBIG, V[0][0]=0
                    umA = FBIG; uwA = 1.0f; dmA = first ? 0.0f : FBIG; dwA = 1.0f;
                    umB = FBIG; uwB = 1.0f; dmB = FBIG; dwB = 1.0f;
                } else if (l == 0) {            // cross-warp pipeline
                    umA = lzmA; uwA = lzwA; umB = lzmB; uwB = lzwB;
                    dmA = first ? FBIG : lzhm; dwA = first ? 1.0f : lzhw;
                    dmB = lzmA; dwB = lzwA;
                } else {                        // intra-warp pipeline
                    umA = rxmA; uwA = rxwA; umB = rxmB; uwB = rxwB;
                    dmA = first ? FBIG : holdm; dwA = first ? 1.0f : holdw;
                    dmB = rxmA; dwB = rxwA;
                }
                int ia = min(max(2 * p, 0), 254);
                float oA = s_o[ia], oB = s_o[ia + 1];
                float wA[8], wB[8];
                // ---- col A ----
                {
                    float um = umA, uw = uwA, dm = dmA, dw = dwA;
                    #pragma unroll
                    for (int r = 0; r < 4; ++r) {
                        float ms = fminf(mm[r], fminf(um, dm));
                        float kk = ms * K2;
                        float tl = ww[r] * ex2(fmaf(-K2, mm[r], kk));
                        float tu = uw    * ex2(fmaf(-K2, um,  kk));
                        float td = dw    * ex2(fmaf(-K2, dm,  kk));
                        float nw = tl + tu + td;
                        float rc = rcpa(nw);
                        wA[2*r] = tu * rc; wA[2*r+1] = tl * rc;
                        float d  = ti[r] - oA;
                        float nm = fmaf(d, d, ms);
                        dm = mm[r]; dw = ww[r];
                        mm[r] = nm; ww[r] = nw;
                        um = nm; uw = nw;
                    }
                }
                float m3A = mm[3], w3A = ww[3];
                // ---- col B (left = col A outputs, in-register) ----
                {
                    float um = umB, uw = uwB, dm = dmB, dw = dwB;
                    #pragma unroll
                    for (int r = 0; r < 4; ++r) {
                        float ms = fminf(mm[r], fminf(um, dm));
                        float kk = ms * K2;
                        float tl = ww[r] * ex2(fmaf(-K2, mm[r], kk));
                        float tu = uw    * ex2(fmaf(-K2, um,  kk));
                        float td = dw    * ex2(fmaf(-K2, dm,  kk));
                        float nw = tl + tu + td;
                        float rc = rcpa(nw);
                        wB[2*r] = tu * rc; wB[2*r+1] = tl * rc;
                        float d  = ti[r] - oB;
                        float nm = fmaf(d, d, ms);
                        dm = mm[r]; dw = ww[r];
                        mm[r] = nm; ww[r] = nw;
                        um = nm; uw = nw;
                    }
                }
                float m3B = mm[3], w3B = ww[3];
                if (act) {
                    float4* pa = Wb + ((((2 * p) << 6) + tid) << 1);
                    pa[0] = make_float4(wA[0], wA[1], wA[2], wA[3]);
                    pa[1] = make_float4(wA[4], wA[5], wA[6], wA[7]);
                    float4* pb = Wb + ((((2 * p + 1) << 6) + tid) << 1);
                    pb[0] = make_float4(wB[0], wB[1], wB[2], wB[3]);
                    pb[1] = make_float4(wB[4], wB[5], wB[6], wB[7]);
                    if (tid == 63 && p == 127)
                        s_vnn = fmaf(-GLN2, lg2(w3B), m3B);   // V[N][N]
                }
                float hmA = act ? m3A : FBIG, hwA = act ? w3A : 1.0f;
                float hmB = act ? m3B : FBIG, hwB = act ? w3B : 1.0f;
                holdm = rxmB; holdw = rxwB;     // col 2p+2 of prev pair -> next diag
                rxmA = __shfl_up_sync(FULL, hmA, 1);
                rxwA = __shfl_up_sync(FULL, hwA, 1);
                rxmB = __shfl_up_sync(FULL, hmB, 1);
                rxwB = __shfl_up_sync(FULL, hwB, 1);
                if (tid == 31) {
                    s_f[n & 1][0] = hmA; s_f[n & 1][1] = hwA;
                    s_f[n & 1][2] = hmB; s_f[n & 1][3] = hwB;
                }
                __syncthreads();
                if (w == 1 && l == 0) {
                    lzhm = lzmB; lzhw = lzwB;
                    lzmA = s_f[n & 1][0]; lzwA = s_f[n & 1][1];
                    lzmB = s_f[n & 1][2]; lzwB = s_f[n & 1][3];
                }
            }
            // renormalize every 4 iters (8 cols): bounds w; value-preserving
            #pragma unroll
            for (int r = 0; r < 4; ++r) {
                mm[r] = fmaf(-GLN2, lg2(ww[r]), mm[r]); ww[r] = 1.0f;
            }
        }
    }

    // ===== BACKWARD: weight-flow (MUFU-free), 4 rows/lane, 2 cols/iter =========
    float sumE = 0.0f;
    {
        float pl[4], pdp[4];
        #pragma unroll
        for (int r = 0; r < 4; ++r) { pl[r] = 0.0f; pdp[r] = 0.0f; }
        float rxpuA = 0, rxpuB = 0, rxpdA = 0, rxpdB = 0, holdpd = 0;
        float lzpuA = 0, lzpuB = 0, lzpdA = 0, lzpdB = 0, lzhold = 0;
        float4 cA0, cA1, cB0, cB1, nA0, nA1, nB0, nB1;
        const float4 f4z = make_float4(0, 0, 0, 0);
        const int goff = 63 - tid;

        {   // load iter 0
            int p0 = -tid;
            bool a = (unsigned)p0 < 128u;
            int ja = min(max(255 - 2 * p0, 0), 255);
            int jb = min(max(254 - 2 * p0, 0), 255);
            const float4* pa = Wb + (((ja << 6) + goff) << 1);
            const float4* pb = Wb + (((jb << 6) + goff) << 1);
            cA0 = a ? __ldg(pa) : f4z;  cA1 = a ? __ldg(pa + 1) : f4z;
            cB0 = a ? __ldg(pb) : f4z;  cB1 = a ? __ldg(pb + 1) : f4z;
        }

        for (int n = 0; n < 191; ++n) {
            {   // prefetch iter n+1 (one full iteration of lead)
                int p1 = n + 1 - tid;
                bool a = (unsigned)p1 < 128u;
                int ja = min(max(255 - 2 * p1, 0), 255);
                int jb = min(max(254 - 2 * p1, 0), 255);
                const float4* pa = Wb + (((ja << 6) + goff) << 1);
                const float4* pb = Wb + (((jb << 6) + goff) << 1);
                nA0 = a ? __ldg(pa) : f4z;  nA1 = a ? __ldg(pa + 1) : f4z;
                nB0 = a ? __ldg(pb) : f4z;  nB1 = a ? __ldg(pb + 1) : f4z;
            }
            const int p = n - tid;
            const bool act   = (unsigned)p < 128u;
            const bool first = (n == tid);
            if (first) {
                #pragma unroll
                for (int r = 0; r < 4; ++r) { pl[r] = 0.0f; pdp[r] = 0.0f; }
            }
            float puA_in, pdA_in, puB_in, pdB_in;
            if (tid == 0) { puA_in = 0; pdA_in = 0; puB_in = 0; pdB_in = 0; }
            else if (l == 0) {
                puA_in = lzpuA; pdA_in = first ? 0.0f : lzhold;
                puB_in = lzpuB; pdB_in = lzpdA;
            } else {
                puA_in = rxpuA; pdA_in = first ? 0.0f : holdpd;
                puB_in = rxpuB; pdB_in = rxpdA;
            }
            // weight mapping: row r <-> forward component 3-r
            float wuA[4], wlA[4], wuB[4], wlB[4];
            wuA[0] = cA1.z; wlA[0] = cA1.w;  wuA[1] = cA1.x; wlA[1] = cA1.y;
            wuA[2] = cA0.z; wlA[2] = cA0.w;  wuA[3] = cA0.x; wlA[3] = cA0.y;
            wuB[0] = cB1.z; wlB[0] = cB1.w;  wuB[1] = cB1.x; wlB[1] = cB1.y;
            wuB[2] = cB0.z; wlB[2] = cB0.w;  wuB[3] = cB0.x; wlB[3] = cB0.y;
            const float wqA = (float)(2 * n - 6 * tid);   // (i-j) row0 colA
            float puA3, pdA3, puB3, pdB3;
            // ---- col A ----
            {
                float pu_in = puA_in, pd_in = pdA_in;
                #pragma unroll
                for (int r = 0; r < 4; ++r) {
                    float E = pu_in + pl[r] + pd_in;
                    if (tid == 0 && n == 0 && r == 0) E = 1.0f;   // E[N][N]
                    float wd = 1.0f - wuA[r] - wlA[r];
                    float pu = E * wuA[r], pd = E * wd, pln = E * wlA[r];
                    if (!act) { pu = 0; pd = 0; pln = 0; E = 0; }
                    float wq = wqA - (float)r;
                    sumE = fmaf(E, wq * wq, sumE);
                    pd_in = pdp[r]; pdp[r] = pd; pl[r] = pln; pu_in = pu;
                }
                puA3 = pu_in; pdA3 = pdp[3];
            }
            // ---- col B ----
            {
                float pu_in = puB_in, pd_in = pdB_in;
                #pragma unroll
                for (int r = 0; r < 4; ++r) {
                    float E = pu_in + pl[r] + pd_in;
                    float wd = 1.0f - wuB[r] - wlB[r];
                    float pu = E * wuB[r], pd = E * wd, pln = E * wlB[r];
                    if (!act) { pu = 0; pd = 0; pln = 0; E = 0; }
                    float wq = wqA + 1.0f - (float)r;
                    sumE = fmaf(E, wq * wq, sumE);
                    pd_in = pdp[r]; pdp[r] = pd; pl[r] = pln; pu_in = pu;
                }
                puB3 = pu_in; pdB3 = pdp[3];
            }
            holdpd = rxpdB;
            rxpuA = __shfl_up_sync(FULL, puA3, 1);
            rxpuB = __shfl_up_sync(FULL, puB3, 1);
            rxpdA = __shfl_up_sync(FULL, pdA3, 1);
            rxpdB = __shfl_up_sync(FULL, pdB3, 1);
            if (tid == 31) {
                s_b[n & 1][0] = puA3; s_b[n & 1][1] = puB3;
                s_b[n & 1][2] = pdA3; s_b[n & 1][3] = pdB3;
            }
            __syncthreads();
            if (w == 1 && l == 0) {
                lzhold = lzpdB;
                lzpuA = s_b[n & 1][0]; lzpuB = s_b[n & 1][1];
                lzpdA = s_b[n & 1][2]; lzpdB = s_b[n & 1][3];
            }
            cA0 = nA0; cA1 = nA1; cB0 = nB0; cB1 = nB1;
        }
    }

    // ---- reduce sum(E * omega) ----
    #pragma unroll
    for (int off = 16; off > 0; off >>= 1)
        sumE += __shfl_down_sync(FULL, sumE, off);
    if (l == 0) s_red[w] = sumE;
    __syncthreads();

    if (tid == 0) {
        g_partV[b] = s_vnn;
        g_partE[b] = s_red[0] + s_red[1];
        __threadfence();
        unsigned tk = atomicAdd(&g_ticket, 1u);
        s_last = (tk == BB - 1) ? 1 : 0;
    }
    __syncthreads();
    if (s_last && tid < 32) {
        __threadfence();
        float sv = __ldcg(&g_partV[tid]) + __ldcg(&g_partV[tid + 32]);
        float se = __ldcg(&g_partE[tid]) + __ldcg(&g_partE[tid + 32]);
        #pragma unroll
        for (int off = 16; off > 0; off >>= 1) {
            sv += __shfl_down_sync(FULL, sv, off);
            se += __shfl_down_sync(FULL, se, off);
        }
        if (tid == 0) {
            float loss_shape    = sv * (1.0f / (float)BB);
            float loss_temporal = se * (1.0f / ((float)BB * (float)(NN * NN)));
            out[0] = 0.5f * loss_shape + 0.5f * loss_temporal;
            g_ticket = 0;   // reset for graph replay
        }
    }
}

extern "C" void kernel_launch(void* const* d_in, const int* in_sizes, int n_in,
                              void* d_out, int out_size) {
    const float* y_pred = (const float*)d_in[0];
    const float* y_true = (const float*)d_in[1];
    dilate_fb_kernel<<<BB, 64>>>(y_pred, y_true, (float*)d_out);
}

// round 16
// speedup vs baseline: 1.3755x; 1.3755x over previous
#include <cuda_runtime.h>

#define NN 256
#define BB 64
#define FBIG 1e8f
#define K2   144.269504089f     // (1/gamma)*log2(e), gamma = 0.01
#define GLN2 0.006931471806f    // gamma*ln(2)
#define TT   320
#define FULL 0xffffffffu

// Softmin-weight scratch, time-major (R13 layout): per (iter t, group V4):
// p[0]=(wu0,wl0,wu1,wl1), p[1]=(wu2,wl2,wu3,wl3) for rows 4*V4+1..4*V4+4,
// column q = t - V4 + 1. wd = 1-wu-wl. 42 MB -> L2-resident.
__device__ float4 g_W[BB * TT * 64 * 2];
__device__ float g_partV[BB];
__device__ float g_partE[BB];
__device__ unsigned g_ticket = 0;

__device__ __forceinline__ float ex2(float x){ float r; asm("ex2.approx.f32 %0,%1;":"=f"(r):"f"(x)); return r; }
__device__ __forceinline__ float lg2(float x){ float r; asm("lg2.approx.f32 %0,%1;":"=f"(r):"f"(x)); return r; }
__device__ __forceinline__ float rcpa(float x){ float r; asm("rcp.approx.f32 %0,%1;":"=f"(r):"f"(x)); return r; }

__global__ __launch_bounds__(64, 1) void dilate_fb_kernel(
    const float* __restrict__ y_pred,
    const float* __restrict__ y_true,
    float* __restrict__ out)
{
    __shared__ float s_o[NN], s_t[NN];
    __shared__ float s_fm[2], s_fw[2];      // fwd cross-warp handoff, parity
    __shared__ float s_vnn;
    __shared__ int   s_last;

    const int b   = blockIdx.x;
    const int tid = threadIdx.x;      // fwd virtual lane V; owns rows 4V+1..4V+4
    const int w   = tid >> 5;
    const int l   = tid & 31;

    for (int x = tid; x < NN; x += 64) {
        s_o[x] = y_pred[b * NN + x];
        s_t[x] = y_true[b * NN + x];
    }
    __syncthreads();

    const float ti0 = s_t[4 * tid];
    const float ti1 = s_t[4 * tid + 1];
    const float ti2 = s_t[4 * tid + 2];
    const float ti3 = s_t[4 * tid + 3];
    float4* __restrict__ Wb = g_W + (size_t)b * (TT * 64 * 2);

    // ===== FORWARD (exact R13): (m,w) soft-min, 4 rows/lane, 2-warp ladder =====
    {
        float mm0 = FBIG, mm1 = FBIG, mm2 = FBIG, mm3 = FBIG;
        float ww0 = 1.0f, ww1 = 1.0f, ww2 = 1.0f, ww3 = 1.0f;
        float shAm = FBIG, shAw = 1.0f, shBm = FBIG, shBw = 1.0f;
        float lzum = FBIG, lzuw = 1.0f, lzdm = FBIG, lzdw = 1.0f;

        for (int c = 0; c < TT / 8; ++c) {
            float o_pre[8];
            #pragma unroll
            for (int k = 0; k < 8; ++k) {
                int x = c * 8 + k - tid;
                x = min(max(x, 0), NN - 1);
                o_pre[k] = s_o[x];
            }
            #pragma unroll
            for (int k = 0; k < 8; ++k) {
                const int t = c * 8 + k;
                const bool act   = (unsigned)(t - tid) < NN;
                const bool first = (t == tid);
                if (first) { mm0 = FBIG; mm1 = FBIG; mm2 = FBIG; mm3 = FBIG;
                             ww0 = 1.0f; ww1 = 1.0f; ww2 = 1.0f; ww3 = 1.0f; }
                float um, uw, dm, dw;
                if (l == 0) { um = (w == 0) ? FBIG : lzum; uw = (w == 0) ? 1.0f : lzuw;
                              dm = (w == 0) ? FBIG : lzdm; dw = (w == 0) ? 1.0f : lzdw; }
                else        { um = shAm; uw = shAw; dm = shBm; dw = shBw; }
                if (first) { dm = (tid == 0) ? 0.0f : FBIG; dw = 1.0f; }   // V[0][0]=0
                const float oj = o_pre[k];
                float wu_s0, wl_s0, wu_s1, wl_s1, wu_s2, wl_s2, wu_s3, wl_s3;
                // row0
                {
                    float ms = fminf(mm0, fminf(um, dm));
                    float kk = ms * K2;
                    float tl = ww0 * ex2(fmaf(-K2, mm0, kk));
                    float tu = uw  * ex2(fmaf(-K2, um,  kk));
                    float td = dw  * ex2(fmaf(-K2, dm,  kk));
                    float nw = tl + tu + td;
                    float rc = rcpa(nw);
                    wu_s0 = tu * rc; wl_s0 = tl * rc;
                    float d = ti0 - oj;
                    float nm = fmaf(d, d, ms);
                    dm = mm0; dw = ww0;
                    mm0 = nm; ww0 = nw;
                    um = nm;  uw = nw;
                }
                // row1
                {
                    float ms = fminf(mm1, fminf(um, dm));
                    float kk = ms * K2;
                    float tl = ww1 * ex2(fmaf(-K2, mm1, kk));
                    float tu = uw  * ex2(fmaf(-K2, um,  kk));
                    float td = dw  * ex2(fmaf(-K2, dm,  kk));
                    float nw = tl + tu + td;
                    float rc = rcpa(nw);
                    wu_s1 = tu * rc; wl_s1 = tl * rc;
                    float d = ti1 - oj;
                    float nm = fmaf(d, d, ms);
                    dm = mm1; dw = ww1;
                    mm1 = nm; ww1 = nw;
                    um = nm;  uw = nw;
                }
                // row2
                {
                    float ms = fminf(mm2, fminf(um, dm));
                    float kk = ms * K2;
                    float tl = ww2 * ex2(fmaf(-K2, mm2, kk));
                    float tu = uw  * ex2(fmaf(-K2, um,  kk));
                    float td = dw  * ex2(fmaf(-K2, dm,  kk));
                    float nw = tl + tu + td;
                    float rc = rcpa(nw);
                    wu_s2 = tu * rc; wl_s2 = tl * rc;
                    float d = ti2 - oj;
                    float nm = fmaf(d, d, ms);
                    dm = mm2; dw = ww2;
                    mm2 = nm; ww2 = nw;
                    um = nm;  uw = nw;
                }
                // row3
                {
                    float ms = fminf(mm3, fminf(um, dm));
                    float kk = ms * K2;
                    float tl = ww3 * ex2(fmaf(-K2, mm3, kk));
                    float tu = uw  * ex2(fmaf(-K2, um,  kk));
                    float td = dw  * ex2(fmaf(-K2, dm,  kk));
                    float nw = tl + tu + td;
                    float rc = rcpa(nw);
                    wu_s3 = tu * rc; wl_s3 = tl * rc;
                    float d = ti3 - oj;
                    float nm = fmaf(d, d, ms);
                    mm3 = nm; ww3 = nw;
                }
                if (act) {
                    float4* p = Wb + (((t << 6) + tid) << 1);
                    p[0] = make_float4(wu_s0, wl_s0, wu_s1, wl_s1);
                    p[1] = make_float4(wu_s2, wl_s2, wu_s3, wl_s3);
                    if (tid == 63 && t == NN + 62)
                        s_vnn = fmaf(-GLN2, lg2(ww3), mm3);     // V[N][N]
                }
                float hm = act ? mm3 : FBIG;
                float hw = act ? ww3 : 1.0f;
                shBm = shAm; shBw = shAw;
                shAm = __shfl_up_sync(FULL, hm, 1);
                shAw = __shfl_up_sync(FULL, hw, 1);
                if (l == 31 && w == 0) { s_fm[t & 1] = hm; s_fw[t & 1] = hw; }
                __syncthreads();
                if (w == 1) { lzdm = lzum; lzdw = lzuw;
                              lzum = s_fm[t & 1]; lzuw = s_fw[t & 1]; }
            }
            // renormalize every 8 cols: m <- folded V, w <- 1 (bounds w)
            mm0 = fmaf(-GLN2, lg2(ww0), mm0); ww0 = 1.0f;
            mm1 = fmaf(-GLN2, lg2(ww1), mm1); ww1 = 1.0f;
            mm2 = fmaf(-GLN2, lg2(ww2), mm2); ww2 = 1.0f;
            mm3 = fmaf(-GLN2, lg2(ww3), mm3); ww3 = 1.0f;
        }
    }

    // ===== BACKWARD: single-warp weight-flow, 8 rows/lane, sync-free ==========
    // Original coords. Lane l owns rows 249-8l..256-8l (r=0 bottom: i=256-8l).
    // Iteration t: column j = 256-(t-l). Weight slots: group A=63-2l at forward
    // slot 318-t-l, group B=62-2l at 317-t-l; A(t+1) == B(t) (rolling reuse).
    float sumE = 0.0f;
    if (w == 0) {
        float pl[8], pdp[8];
        #pragma unroll
        for (int r = 0; r < 8; ++r) { pl[r] = 0.0f; pdp[r] = 0.0f; }
        float shApu = 0.0f, shApd = 0.0f, shBpd = 0.0f;
        const int gA = 63 - 2 * l, gB = 62 - 2 * l;
        const float4 f4z = make_float4(0, 0, 0, 0);
        float4 A0, A1, B0, B1, nB0, nB1;

        // prologue: A(t=0) = slot(318-l, gA) [only lane 0 active at t=0];
        // B(t=0) = slot(317-l, gB); nB = B(t=1) = slot(316-l, gB)
        {
            const float4* pA = Wb + ((((318 - l) << 6) + gA) << 1);
            bool aA = (l == 0);
            A0 = aA ? __ldg(pA)     : f4z;
            A1 = aA ? __ldg(pA + 1) : f4z;
            const float4* pB = Wb + ((((317 - l) << 6) + gB) << 1);
            bool aB = ((unsigned)(1 - l) < 257u);
            B0 = aB ? __ldg(pB)     : f4z;
            B1 = aB ? __ldg(pB + 1) : f4z;
            const float4* pN = Wb + ((((316 - l) << 6) + gB) << 1);
            bool aN = ((unsigned)(2 - l) < 257u);
            nB0 = aN ? __ldg(pN)     : f4z;
            nB1 = aN ? __ldg(pN + 1) : f4z;
        }

        #pragma unroll 4
        for (int t = 0; t < 287; ++t) {
            // issue load for iteration t+2's B pair (slot 315-t-l)
            float4 mB0, mB1;
            {
                int s = 315 - t - l;
                bool a2 = ((unsigned)(t + 3 - l) < 257u) && (s >= 0);
                const float4* p = Wb + (((s << 6) + gB) << 1);
                mB0 = a2 ? __ldg(p)     : f4z;
                mB1 = a2 ? __ldg(p + 1) : f4z;
            }
            const bool act = (unsigned)(t - l) < NN;
            float pu_in = (l == 0) ? 0.0f : shApu;   // lane l-1 pu7 @ t-1
            float pd_in = (l == 0) ? 0.0f : shBpd;   // lane l-1 pd7 @ t-2
            // weight mapping: r ascending = rows bottom-up within band
            float wu_[8], wl_[8];
            wu_[0] = A1.z; wl_[0] = A1.w;  wu_[1] = A1.x; wl_[1] = A1.y;
            wu_[2] = A0.z; wl_[2] = A0.w;  wu_[3] = A0.x; wl_[3] = A0.y;
            wu_[4] = B1.z; wl_[4] = B1.w;  wu_[5] = B1.x; wl_[5] = B1.y;
            wu_[6] = B0.z; wl_[6] = B0.w;  wu_[7] = B0.x; wl_[7] = B0.y;
            const float wqb = (float)(t - 9 * l);    // (i-j) for r=0
            #pragma unroll
            for (int r = 0; r < 8; ++r) {
                float E = pu_in + pl[r] + pd_in;
                if (l == 0 && t == 0 && r == 0) E = 1.0f;   // E[N][N]
                if (!act) E = 0.0f;
                float wd = 1.0f - wu_[r] - wl_[r];
                float pu = E * wu_[r], pd = E * wd, pln = E * wl_[r];
                float wq = wqb - (float)r;
                sumE = fmaf(E, wq * wq, sumE);
                pd_in = pdp[r]; pdp[r] = pd; pl[r] = pln; pu_in = pu;
            }
            float pu7 = pu_in, pd7 = pdp[7];
            shBpd = shApd;
            shApd = __shfl_up_sync(FULL, pd7, 1);
            shApu = __shfl_up_sync(FULL, pu7, 1);
            // rotate weight pipeline: A <- B <- nB <- just-loaded
            A0 = B0; A1 = B1; B0 = nB0; B1 = nB1; nB0 = mB0; nB1 = mB1;
        }
        // warp reduction (lane 0 ends with the total)
        #pragma unroll
        for (int off = 16; off > 0; off >>= 1)
            sumE += __shfl_down_sync(FULL, sumE, off);
    }
    __syncthreads();   // warp 1 waits here during the backward

    // ---- per-block partials + deterministic last-block finalize ----
    if (tid == 0) {
        g_partV[b] = s_vnn;
        g_partE[b] = sumE;            // tid0 = warp0 lane0 holds the reduced sum
        __threadfence();
        unsigned tk = atomicAdd(&g_ticket, 1u);
        s_last = (tk == BB - 1) ? 1 : 0;
    }
    __syncthreads();
    if (s_last && tid < 32) {
        __threadfence();
        float sv = __ldcg(&g_partV[tid]) + __ldcg(&g_partV[tid + 32]);
        float se = __ldcg(&g_partE[tid]) + __ldcg(&g_partE[tid + 32]);
        #pragma unroll
        for (int off = 16; off > 0; off >>= 1) {
            sv += __shfl_down_sync(FULL, sv, off);
            se += __shfl_down_sync(FULL, se, off);
        }
        if (tid == 0) {
            float loss_shape    = sv * (1.0f / (float)BB);
            float loss_temporal = se * (1.0f / ((float)BB * (float)(NN * NN)));
            out[0] = 0.5f * loss_shape + 0.5f * loss_temporal;
            g_ticket = 0;   // reset for graph replay
        }
    }
}

extern "C" void kernel_launch(void* const* d_in, const int* in_sizes, int n_in,
                              void* d_out, int out_size) {
    const float* y_pred = (const float*)d_in[0];
    const float* y_true = (const float*)d_in[1];
    dilate_fb_kernel<<<BB, 64>>>(y_pred, y_true, (float*)d_out);
}